// round 2
// baseline (speedup 1.0000x reference)
#include <cuda_runtime.h>

#define DIMC 512
#define NH   8
#define HD   64
#define BATCH 4
#define NQ   1024
#define NKV  1024

// ---------------- scratch (device globals: no allocation allowed) ----------
__device__ float g_q [BATCH*NH*NQ *HD];
__device__ float g_k [BATCH*NH*NKV*HD];
__device__ float g_v [BATCH*NH*NKV*HD];
__device__ float g_xo[BATCH*NQ*DIMC];
__device__ float g_lam[NH/2];

// ---------------- lambda ---------------------------------------------------
__global__ void lam_kernel(const float* __restrict__ lq1, const float* __restrict__ lk1,
                           const float* __restrict__ lq2, const float* __restrict__ lk2)
{
    int p = threadIdx.x;
    if (p < NH/2) {
        float a = 0.f, c = 0.f;
        for (int d = 0; d < HD; d++) {
            a += lq1[p*HD+d] * lk1[p*HD+d];
            c += lq2[p*HD+d] * lk2[p*HD+d];
        }
        g_lam[p] = __expf(a) - __expf(c) + 0.8f;
    }
}

// ---------------- GEMM: C = A[M,K] @ W[N,K]^T + bias -----------------------
// mode 0: C row-major [M, 512] ; mode 1: C in [B,H,N,HD] attention layout
#define BM 64
#define BN 64
#define BKK 16

__global__ __launch_bounds__(128) void gemm_kernel(
    const float* __restrict__ A, const float* __restrict__ W,
    const float* __restrict__ bias, float* __restrict__ C, int mode)
{
    __shared__ __align__(16) float As[BKK][BM+4];
    __shared__ __align__(16) float Bs[BKK][BN+4];

    int tid = threadIdx.x;
    int bm = blockIdx.x * BM;
    int bn = blockIdx.y * BN;
    int tx = tid & 7;       // 0..7 (col group of 8)
    int ty = tid >> 3;      // 0..15 (row group of 4)

    float acc[4][8];
#pragma unroll
    for (int i = 0; i < 4; i++)
#pragma unroll
        for (int j = 0; j < 8; j++) acc[i][j] = 0.f;

    int lr = tid >> 1;            // 0..63
    int lc = (tid & 1) * 8;       // 0 or 8

    for (int k0 = 0; k0 < DIMC; k0 += BKK) {
        float4 a0 = *(const float4*)(A + (size_t)(bm+lr)*DIMC + k0 + lc);
        float4 a1 = *(const float4*)(A + (size_t)(bm+lr)*DIMC + k0 + lc + 4);
        float4 b0 = *(const float4*)(W + (size_t)(bn+lr)*DIMC + k0 + lc);
        float4 b1 = *(const float4*)(W + (size_t)(bn+lr)*DIMC + k0 + lc + 4);
        As[lc+0][lr]=a0.x; As[lc+1][lr]=a0.y; As[lc+2][lr]=a0.z; As[lc+3][lr]=a0.w;
        As[lc+4][lr]=a1.x; As[lc+5][lr]=a1.y; As[lc+6][lr]=a1.z; As[lc+7][lr]=a1.w;
        Bs[lc+0][lr]=b0.x; Bs[lc+1][lr]=b0.y; Bs[lc+2][lr]=b0.z; Bs[lc+3][lr]=b0.w;
        Bs[lc+4][lr]=b1.x; Bs[lc+5][lr]=b1.y; Bs[lc+6][lr]=b1.z; Bs[lc+7][lr]=b1.w;
        __syncthreads();

#pragma unroll
        for (int kk = 0; kk < BKK; kk++) {
            float4 ar  = *(const float4*)&As[kk][ty*4];
            float4 br0 = *(const float4*)&Bs[kk][tx*8];
            float4 br1 = *(const float4*)&Bs[kk][tx*8+4];
            float av[4] = {ar.x, ar.y, ar.z, ar.w};
            float bv[8] = {br0.x, br0.y, br0.z, br0.w, br1.x, br1.y, br1.z, br1.w};
#pragma unroll
            for (int i = 0; i < 4; i++)
#pragma unroll
                for (int j = 0; j < 8; j++)
                    acc[i][j] += av[i] * bv[j];
        }
        __syncthreads();
    }

    int colb = bn + tx*8;
    float bsv[8];
#pragma unroll
    for (int j = 0; j < 8; j++) bsv[j] = bias[colb+j];

#pragma unroll
    for (int i = 0; i < 4; i++) {
        int row = bm + ty*4 + i;
        float4 o0, o1;
        o0.x = acc[i][0]+bsv[0]; o0.y = acc[i][1]+bsv[1];
        o0.z = acc[i][2]+bsv[2]; o0.w = acc[i][3]+bsv[3];
        o1.x = acc[i][4]+bsv[4]; o1.y = acc[i][5]+bsv[5];
        o1.z = acc[i][6]+bsv[6]; o1.w = acc[i][7]+bsv[7];
        if (mode == 0) {
            *(float4*)(C + (size_t)row*DIMC + colb)     = o0;
            *(float4*)(C + (size_t)row*DIMC + colb + 4) = o1;
        } else {
            int b  = row >> 10, nq = row & 1023;
            int h  = colb >> 6, hd = colb & 63;
            float* dst = C + (((size_t)(b*NH + h)*NQ + nq)*HD + hd);
            *(float4*)dst       = o0;
            *(float4*)(dst + 4) = o1;
        }
    }
}

// ---------------- fused differential flash attention ----------------------
// grid: (NQ/32, NH/2 pairs, B) ; block 256 threads
// per (b, pair p): heads h1=p, h2=p+4
//   acc1 = P1@V1, acc2 = P2@V1, acc3 = P2@V2 (online softmax per head)
//   out[h1] = (1+alpha)/l1 * acc1 - alpha*lam/l2 * acc2
//   out[h2] = acc3 / l2
__global__ __launch_bounds__(256) void attn_kernel(
    const int* __restrict__ coords_q, const int* __restrict__ coords_k,
    const float* __restrict__ alpha_map, const float* __restrict__ rpe)
{
    extern __shared__ __align__(16) float sm[];
    float* sQ1 = sm;                 // [32][68]
    float* sQ2 = sQ1 + 32*68;
    float* sK1 = sQ2 + 32*68;        // [64][68]
    float* sK2 = sK1 + 64*68;
    float* sV1 = sK2 + 64*68;
    float* sV2 = sV1 + 64*68;
    float* sS1 = sV2 + 64*68;        // [32][66]
    float* sS2 = sS1 + 32*66;
    int*   sCq = (int*)(sS2 + 32*66); // [32][2]
    int*   sCk = sCq + 64;            // [64][2]

    int tid = threadIdx.x;
    int qb  = blockIdx.x * 32;
    int p   = blockIdx.y;
    int b   = blockIdx.z;
    int h1  = p, h2 = p + 4;

    // load Q tiles (32 x 64 per head)
    {
        int r  = tid >> 3;
        int d0 = (tid & 7) * 8;
        const float* q1g = g_q + ((size_t)(b*NH+h1)*NQ + qb + r)*HD + d0;
        const float* q2g = g_q + ((size_t)(b*NH+h2)*NQ + qb + r)*HD + d0;
        *(float4*)&sQ1[r*68+d0]   = *(const float4*)(q1g);
        *(float4*)&sQ1[r*68+d0+4] = *(const float4*)(q1g+4);
        *(float4*)&sQ2[r*68+d0]   = *(const float4*)(q2g);
        *(float4*)&sQ2[r*68+d0+4] = *(const float4*)(q2g+4);
    }
    if (tid < 64) sCq[tid] = coords_q[(size_t)(b*NQ + qb)*2 + tid];

    int r  = tid >> 3;     // q row 0..31
    int cg = tid & 7;      // column group 0..7
    int d0 = cg * 8;

    float acc1[8], acc2[8], acc3[8];
#pragma unroll
    for (int j = 0; j < 8; j++) { acc1[j]=0.f; acc2[j]=0.f; acc3[j]=0.f; }
    float m1 = -1e30f, l1 = 0.f, m2 = -1e30f, l2 = 0.f;

    for (int kb = 0; kb < NKV; kb += 64) {
        // stage K/V tiles
        {
            int kr = tid >> 2;
            int dd = (tid & 3) * 16;
            const float* k1g = g_k + ((size_t)(b*NH+h1)*NKV + kb + kr)*HD + dd;
            const float* k2g = g_k + ((size_t)(b*NH+h2)*NKV + kb + kr)*HD + dd;
            const float* v1g = g_v + ((size_t)(b*NH+h1)*NKV + kb + kr)*HD + dd;
            const float* v2g = g_v + ((size_t)(b*NH+h2)*NKV + kb + kr)*HD + dd;
#pragma unroll
            for (int i = 0; i < 4; i++) {
                *(float4*)&sK1[kr*68+dd+4*i] = *(const float4*)(k1g+4*i);
                *(float4*)&sK2[kr*68+dd+4*i] = *(const float4*)(k2g+4*i);
                *(float4*)&sV1[kr*68+dd+4*i] = *(const float4*)(v1g+4*i);
                *(float4*)&sV2[kr*68+dd+4*i] = *(const float4*)(v2g+4*i);
            }
        }
        if (tid < 128) sCk[tid] = coords_k[(size_t)(b*NKV + kb)*2 + tid];
        __syncthreads();

        // scores for 8 columns, both heads
        float s1[8], s2[8];
#pragma unroll
        for (int j = 0; j < 8; j++) { s1[j]=0.f; s2[j]=0.f; }
#pragma unroll
        for (int d = 0; d < 64; d += 4) {
            float4 q1 = *(float4*)&sQ1[r*68+d];
            float4 q2 = *(float4*)&sQ2[r*68+d];
#pragma unroll
            for (int j = 0; j < 8; j++) {
                int kc = d0 + j;
                float4 k1 = *(float4*)&sK1[kc*68+d];
                float4 k2 = *(float4*)&sK2[kc*68+d];
                s1[j] += q1.x*k1.x + q1.y*k1.y + q1.z*k1.z + q1.w*k1.w;
                s2[j] += q2.x*k2.x + q2.y*k2.y + q2.z*k2.z + q2.w*k2.w;
            }
        }
        // scale + RPE bias
        int cqx = sCq[r*2], cqy = sCq[r*2+1];
#pragma unroll
        for (int j = 0; j < 8; j++) {
            int kc = d0 + j;
            int r0 = cqx - sCk[kc*2]   + 128; r0 = min(max(r0, 0), 256);
            int r1 = cqy - sCk[kc*2+1] + 128; r1 = min(max(r1, 0), 256);
            int idx = (r0*257 + r1) * NH;
            s1[j] = s1[j]*0.125f + __ldg(&rpe[idx + h1]);
            s2[j] = s2[j]*0.125f + __ldg(&rpe[idx + h2]);
        }
        // online softmax (per-row stats replicated across the 8 lanes of a row)
        float tm1 = s1[0], tm2 = s2[0];
#pragma unroll
        for (int j = 1; j < 8; j++) { tm1 = fmaxf(tm1, s1[j]); tm2 = fmaxf(tm2, s2[j]); }
#pragma unroll
        for (int o = 1; o < 8; o <<= 1) {
            tm1 = fmaxf(tm1, __shfl_xor_sync(0xffffffffu, tm1, o));
            tm2 = fmaxf(tm2, __shfl_xor_sync(0xffffffffu, tm2, o));
        }
        float m1n = fmaxf(m1, tm1), m2n = fmaxf(m2, tm2);
        float c1 = __expf(m1 - m1n), c2 = __expf(m2 - m2n);
        float sum1 = 0.f, sum2 = 0.f;
#pragma unroll
        for (int j = 0; j < 8; j++) {
            float e1 = __expf(s1[j] - m1n);
            float e2 = __expf(s2[j] - m2n);
            sS1[r*66 + d0 + j] = e1;
            sS2[r*66 + d0 + j] = e2;
            sum1 += e1; sum2 += e2;
        }
#pragma unroll
        for (int o = 1; o < 8; o <<= 1) {
            sum1 += __shfl_xor_sync(0xffffffffu, sum1, o);
            sum2 += __shfl_xor_sync(0xffffffffu, sum2, o);
        }
        l1 = l1*c1 + sum1; l2 = l2*c2 + sum2;
        m1 = m1n; m2 = m2n;
#pragma unroll
        for (int j = 0; j < 8; j++) { acc1[j]*=c1; acc2[j]*=c2; acc3[j]*=c2; }
        __syncwarp();

        // PV accumulation
#pragma unroll 8
        for (int k = 0; k < 64; k++) {
            float p1 = sS1[r*66+k];
            float p2 = sS2[r*66+k];
            float4 va = *(float4*)&sV1[k*68+d0];
            float4 vb = *(float4*)&sV1[k*68+d0+4];
            float4 vc = *(float4*)&sV2[k*68+d0];
            float4 vd = *(float4*)&sV2[k*68+d0+4];
            acc1[0]+=p1*va.x; acc1[1]+=p1*va.y; acc1[2]+=p1*va.z; acc1[3]+=p1*va.w;
            acc1[4]+=p1*vb.x; acc1[5]+=p1*vb.y; acc1[6]+=p1*vb.z; acc1[7]+=p1*vb.w;
            acc2[0]+=p2*va.x; acc2[1]+=p2*va.y; acc2[2]+=p2*va.z; acc2[3]+=p2*va.w;
            acc2[4]+=p2*vb.x; acc2[5]+=p2*vb.y; acc2[6]+=p2*vb.z; acc2[7]+=p2*vb.w;
            acc3[0]+=p2*vc.x; acc3[1]+=p2*vc.y; acc3[2]+=p2*vc.z; acc3[3]+=p2*vc.w;
            acc3[4]+=p2*vd.x; acc3[5]+=p2*vd.y; acc3[6]+=p2*vd.z; acc3[7]+=p2*vd.w;
        }
        __syncthreads();
    }

    // epilogue
    int   qg    = qb + r;
    float alpha = alpha_map[(size_t)b*NQ + qg];
    float lam   = g_lam[p];
    float w1 = (1.f + alpha) / l1;
    float w2 = -alpha * lam / l2;
    float inv2 = 1.f / l2;

    float* o1p = g_xo + ((size_t)(b*NQ + qg))*DIMC + h1*HD + d0;
    float* o2p = g_xo + ((size_t)(b*NQ + qg))*DIMC + h2*HD + d0;
    float4 r0, r1v, r2, r3;
    r0.x = w1*acc1[0]+w2*acc2[0]; r0.y = w1*acc1[1]+w2*acc2[1];
    r0.z = w1*acc1[2]+w2*acc2[2]; r0.w = w1*acc1[3]+w2*acc2[3];
    r1v.x = w1*acc1[4]+w2*acc2[4]; r1v.y = w1*acc1[5]+w2*acc2[5];
    r1v.z = w1*acc1[6]+w2*acc2[6]; r1v.w = w1*acc1[7]+w2*acc2[7];
    r2.x = inv2*acc3[0]; r2.y = inv2*acc3[1]; r2.z = inv2*acc3[2]; r2.w = inv2*acc3[3];
    r3.x = inv2*acc3[4]; r3.y = inv2*acc3[5]; r3.z = inv2*acc3[6]; r3.w = inv2*acc3[7];
    *(float4*)(o1p)   = r0;
    *(float4*)(o1p+4) = r1v;
    *(float4*)(o2p)   = r2;
    *(float4*)(o2p+4) = r3;
}

// ---------------- launch ---------------------------------------------------
#define ATT_SMEM ((2*32*68 + 4*64*68 + 2*32*66)*4 + (64+128)*4)

extern "C" void kernel_launch(void* const* d_in, const int* in_sizes, int n_in,
                              void* d_out, int out_size)
{
    const float* x_q      = (const float*)d_in[0];
    const float* x_kv     = (const float*)d_in[1];
    const int*   coords_q = (const int*)  d_in[2];
    const int*   coords_k = (const int*)  d_in[3];
    const float* alpha    = (const float*)d_in[4];
    const float* Wq       = (const float*)d_in[5];
    const float* bq       = (const float*)d_in[6];
    const float* Wk       = (const float*)d_in[7];
    const float* bk       = (const float*)d_in[8];
    const float* Wv       = (const float*)d_in[9];
    const float* bv       = (const float*)d_in[10];
    const float* lq1      = (const float*)d_in[11];
    const float* lk1      = (const float*)d_in[12];
    const float* lq2      = (const float*)d_in[13];
    const float* lk2      = (const float*)d_in[14];
    const float* rpe      = (const float*)d_in[15];
    const float* Wp       = (const float*)d_in[16];
    const float* bp       = (const float*)d_in[17];
    float* out = (float*)d_out;

    float *qp, *kp, *vp, *xop;
    cudaGetSymbolAddress((void**)&qp,  g_q);
    cudaGetSymbolAddress((void**)&kp,  g_k);
    cudaGetSymbolAddress((void**)&vp,  g_v);
    cudaGetSymbolAddress((void**)&xop, g_xo);

    cudaFuncSetAttribute(attn_kernel,
                         cudaFuncAttributeMaxDynamicSharedMemorySize, ATT_SMEM);

    lam_kernel<<<1, 32>>>(lq1, lk1, lq2, lk2);

    dim3 gg(64, 8);  // M/64 x N/64
    gemm_kernel<<<gg, 128>>>(x_q,  Wq, bq, qp, 1);
    gemm_kernel<<<gg, 128>>>(x_kv, Wk, bk, kp, 1);
    gemm_kernel<<<gg, 128>>>(x_kv, Wv, bv, vp, 1);

    attn_kernel<<<dim3(32, 4, 4), 256, ATT_SMEM>>>(coords_q, coords_k, alpha, rpe);

    gemm_kernel<<<gg, 128>>>(xop, Wp, bp, out, 0);
}

// round 3
// speedup vs baseline: 4.1256x; 4.1256x over previous
#include <cuda_runtime.h>

#define DIMC 512
#define NH   8
#define HD   64
#define BATCH 4
#define NQ   1024
#define NKV  1024

// mid-row pad: conflict-free float4 smem access at 8-float granularity
#define PHYS(d) ((d) + ((((d) >> 5) & 1) << 2))   // d + 4*(d>=32), d in [0,64)

// ---------------- scratch (device globals: no allocation allowed) ----------
__device__ float g_q [BATCH*NH*NQ *HD];
__device__ float g_k [BATCH*NH*NKV*HD];
__device__ float g_v [BATCH*NH*NKV*HD];
__device__ float g_xo[BATCH*NQ*DIMC];
__device__ float g_lam[NH/2];

// ---------------- lambda ---------------------------------------------------
__global__ void lam_kernel(const float* __restrict__ lq1, const float* __restrict__ lk1,
                           const float* __restrict__ lq2, const float* __restrict__ lk2)
{
    int p = threadIdx.x;
    if (p < NH/2) {
        float a = 0.f, c = 0.f;
        for (int d = 0; d < HD; d++) {
            a += lq1[p*HD+d] * lk1[p*HD+d];
            c += lq2[p*HD+d] * lk2[p*HD+d];
        }
        g_lam[p] = __expf(a) - __expf(c) + 0.8f;
    }
}

// ---------------- GEMM body: C = A[M,K] @ W[N,K]^T + bias -----------------
// 64x64 tile, 128 threads, double-buffered global loads, padded smem.
// mode 0: C row-major [M,512] ; mode 1: C into [B,H,N,HD] layout
__device__ __forceinline__ void gemm_body(
    const float* __restrict__ A, const float* __restrict__ W,
    const float* __restrict__ bias, float* __restrict__ C,
    int mode, int bm, int bn)
{
    __shared__ __align__(16) float As[16*68];
    __shared__ __align__(16) float Bs[16*68];

    int tid = threadIdx.x;
    int tx = tid & 7;       // 0..7  column group (8 cols)
    int ty = tid >> 3;      // 0..15 row group (4 rows)

    float acc[4][8];
#pragma unroll
    for (int i = 0; i < 4; i++)
#pragma unroll
        for (int j = 0; j < 8; j++) acc[i][j] = 0.f;

    int lr = tid >> 1;            // 0..63
    int lc = (tid & 1) * 8;       // 0 or 8
    int plr = PHYS(lr);

    const float* Arow = A + (size_t)(bm + lr) * DIMC + lc;
    const float* Wrow = W + (size_t)(bn + lr) * DIMC + lc;

    // prefetch first k-tile
    float4 a0 = *(const float4*)(Arow);
    float4 a1 = *(const float4*)(Arow + 4);
    float4 b0 = *(const float4*)(Wrow);
    float4 b1 = *(const float4*)(Wrow + 4);

    for (int k0 = 0; k0 < DIMC; k0 += 16) {
        // store staged tile (transposed)
        As[(lc+0)*68+plr]=a0.x; As[(lc+1)*68+plr]=a0.y; As[(lc+2)*68+plr]=a0.z; As[(lc+3)*68+plr]=a0.w;
        As[(lc+4)*68+plr]=a1.x; As[(lc+5)*68+plr]=a1.y; As[(lc+6)*68+plr]=a1.z; As[(lc+7)*68+plr]=a1.w;
        Bs[(lc+0)*68+plr]=b0.x; Bs[(lc+1)*68+plr]=b0.y; Bs[(lc+2)*68+plr]=b0.z; Bs[(lc+3)*68+plr]=b0.w;
        Bs[(lc+4)*68+plr]=b1.x; Bs[(lc+5)*68+plr]=b1.y; Bs[(lc+6)*68+plr]=b1.z; Bs[(lc+7)*68+plr]=b1.w;
        __syncthreads();

        if (k0 + 16 < DIMC) {
            a0 = *(const float4*)(Arow + k0 + 16);
            a1 = *(const float4*)(Arow + k0 + 20);
            b0 = *(const float4*)(Wrow + k0 + 16);
            b1 = *(const float4*)(Wrow + k0 + 20);
        }

        int pa = PHYS(ty*4);
        int pb = PHYS(tx*8);
#pragma unroll
        for (int kk = 0; kk < 16; kk++) {
            float4 ar  = *(const float4*)&As[kk*68 + pa];
            float4 br0 = *(const float4*)&Bs[kk*68 + pb];
            float4 br1 = *(const float4*)&Bs[kk*68 + pb + 4];
            float av[4] = {ar.x, ar.y, ar.z, ar.w};
            float bv[8] = {br0.x, br0.y, br0.z, br0.w, br1.x, br1.y, br1.z, br1.w};
#pragma unroll
            for (int i = 0; i < 4; i++)
#pragma unroll
                for (int j = 0; j < 8; j++)
                    acc[i][j] += av[i] * bv[j];
        }
        __syncthreads();
    }

    int colb = bn + tx*8;
    float bsv[8];
#pragma unroll
    for (int j = 0; j < 8; j++) bsv[j] = bias[colb+j];

#pragma unroll
    for (int i = 0; i < 4; i++) {
        int row = bm + ty*4 + i;
        float4 o0, o1;
        o0.x = acc[i][0]+bsv[0]; o0.y = acc[i][1]+bsv[1];
        o0.z = acc[i][2]+bsv[2]; o0.w = acc[i][3]+bsv[3];
        o1.x = acc[i][4]+bsv[4]; o1.y = acc[i][5]+bsv[5];
        o1.z = acc[i][6]+bsv[6]; o1.w = acc[i][7]+bsv[7];
        if (mode == 0) {
            *(float4*)(C + (size_t)row*DIMC + colb)     = o0;
            *(float4*)(C + (size_t)row*DIMC + colb + 4) = o1;
        } else {
            int b  = row >> 10, nq = row & 1023;
            int h  = colb >> 6, hd = colb & 63;
            float* dst = C + (((size_t)(b*NH + h)*NQ + nq)*HD + hd);
            *(float4*)dst       = o0;
            *(float4*)(dst + 4) = o1;
        }
    }
}

// fused Q/K/V projection: blockIdx.z selects which GEMM
__global__ __launch_bounds__(128) void qkv_kernel(
    const float* __restrict__ x_q, const float* __restrict__ x_kv,
    const float* __restrict__ Wq, const float* __restrict__ bq,
    const float* __restrict__ Wk, const float* __restrict__ bk,
    const float* __restrict__ Wv, const float* __restrict__ bv)
{
    int z = blockIdx.z;
    const float* A    = (z == 0) ? x_q : x_kv;
    const float* W    = (z == 0) ? Wq : (z == 1) ? Wk : Wv;
    const float* bias = (z == 0) ? bq : (z == 1) ? bk : bv;
    float* C          = (z == 0) ? g_q : (z == 1) ? g_k : g_v;
    gemm_body(A, W, bias, C, 1, blockIdx.x*64, blockIdx.y*64);
}

__global__ __launch_bounds__(128) void proj_kernel(
    const float* __restrict__ Wp, const float* __restrict__ bp, float* __restrict__ out)
{
    gemm_body(g_xo, Wp, bp, out, 0, blockIdx.x*64, blockIdx.y*64);
}

// ---------------- fused differential flash attention ----------------------
// grid (NQ/32, NH/2, B), 128 threads. Thread: 2 q-rows (rr, rr+16), 8 kv-cols
// (kc = cg + 8j, interleaved -> conflict-free), 8 out dims (d0 = cg*8).
#define ACC8(acc, pp, u, v) \
    acc[0]+=(pp)*(u).x; acc[1]+=(pp)*(u).y; acc[2]+=(pp)*(u).z; acc[3]+=(pp)*(u).w; \
    acc[4]+=(pp)*(v).x; acc[5]+=(pp)*(v).y; acc[6]+=(pp)*(v).z; acc[7]+=(pp)*(v).w;

__global__ __launch_bounds__(128) void attn_kernel(
    const int* __restrict__ coords_q, const int* __restrict__ coords_k,
    const float* __restrict__ alpha_map, const float* __restrict__ rpe)
{
    extern __shared__ __align__(16) float sm[];
    float* sQ1 = sm;                  // [32][68]
    float* sQ2 = sQ1 + 32*68;
    float* sK1 = sQ2 + 32*68;         // [64][68]
    float* sK2 = sK1 + 64*68;
    float* sV1 = sK2 + 64*68;
    float* sV2 = sV1 + 64*68;
    float* sS1 = sV2 + 64*68;         // [32][72]
    float* sS2 = sS1 + 32*72;
    int*   sCk = (int*)(sS2 + 32*72); // [64][2]

    int tid = threadIdx.x;
    int qb  = blockIdx.x * 32;
    int p   = blockIdx.y;
    int b   = blockIdx.z;
    int h1  = p, h2 = p + 4;

    int cg = tid & 7;      // 0..7
    int rr = tid >> 3;     // 0..15 ; rows rr and rr+16
    int d0 = cg * 8;
    int pd0 = PHYS(d0);

    // stage Q tiles (32 x 64 per head) with mid-pad layout
    {
        const float* q1g = g_q + ((size_t)(b*NH+h1)*NQ + qb)*HD;
        const float* q2g = g_q + ((size_t)(b*NH+h2)*NQ + qb)*HD;
        for (int c = tid; c < 512; c += 128) {
            int row = c >> 4, seg = (c & 15) * 4;
            int po = row*68 + PHYS(seg);
            int go = row*HD + seg;
            *(float4*)&sQ1[po] = *(const float4*)(q1g + go);
            *(float4*)&sQ2[po] = *(const float4*)(q2g + go);
        }
    }

    // per-thread query coords (2 rows)
    int cqax = coords_q[((size_t)b*NQ + qb + rr)*2];
    int cqay = coords_q[((size_t)b*NQ + qb + rr)*2 + 1];
    int cqbx = coords_q[((size_t)b*NQ + qb + rr + 16)*2];
    int cqby = coords_q[((size_t)b*NQ + qb + rr + 16)*2 + 1];

    float acc1a[8], acc1b[8], acc2a[8], acc2b[8], acc3a[8], acc3b[8];
#pragma unroll
    for (int j = 0; j < 8; j++) {
        acc1a[j]=0.f; acc1b[j]=0.f; acc2a[j]=0.f;
        acc2b[j]=0.f; acc3a[j]=0.f; acc3b[j]=0.f;
    }
    float m1a=-1e30f, l1a=0.f, m1b=-1e30f, l1b=0.f;
    float m2a=-1e30f, l2a=0.f, m2b=-1e30f, l2b=0.f;

    const float* k1base = g_k + ((size_t)(b*NH+h1)*NKV)*HD;
    const float* k2base = g_k + ((size_t)(b*NH+h2)*NKV)*HD;
    const float* v1base = g_v + ((size_t)(b*NH+h1)*NKV)*HD;
    const float* v2base = g_v + ((size_t)(b*NH+h2)*NKV)*HD;

    for (int kb = 0; kb < NKV; kb += 64) {
        // ---- stage K/V tiles + coords ----
        for (int c = tid; c < 1024; c += 128) {
            int row = c >> 4, seg = (c & 15) * 4;
            int po = row*68 + PHYS(seg);
            int go = (kb + row)*HD + seg;
            *(float4*)&sK1[po] = *(const float4*)(k1base + go);
            *(float4*)&sK2[po] = *(const float4*)(k2base + go);
            *(float4*)&sV1[po] = *(const float4*)(v1base + go);
            *(float4*)&sV2[po] = *(const float4*)(v2base + go);
        }
        sCk[tid] = coords_k[((size_t)b*NKV + kb)*2 + tid];
        __syncthreads();

        // ---- scores: 2 rows x 8 interleaved columns x 2 heads ----
        float s1a[8], s1b[8], s2a[8], s2b[8];
#pragma unroll
        for (int j = 0; j < 8; j++) { s1a[j]=0.f; s1b[j]=0.f; s2a[j]=0.f; s2b[j]=0.f; }

#pragma unroll 4
        for (int d = 0; d < 64; d += 4) {
            int pd = PHYS(d);
            float4 q1A = *(float4*)&sQ1[rr*68 + pd];
            float4 q1B = *(float4*)&sQ1[(rr+16)*68 + pd];
            float4 q2A = *(float4*)&sQ2[rr*68 + pd];
            float4 q2B = *(float4*)&sQ2[(rr+16)*68 + pd];
#pragma unroll
            for (int j = 0; j < 8; j++) {
                int kc = cg + 8*j;
                float4 kk1 = *(float4*)&sK1[kc*68 + pd];
                float4 kk2 = *(float4*)&sK2[kc*68 + pd];
                s1a[j] += q1A.x*kk1.x + q1A.y*kk1.y + q1A.z*kk1.z + q1A.w*kk1.w;
                s1b[j] += q1B.x*kk1.x + q1B.y*kk1.y + q1B.z*kk1.z + q1B.w*kk1.w;
                s2a[j] += q2A.x*kk2.x + q2A.y*kk2.y + q2A.z*kk2.z + q2A.w*kk2.w;
                s2b[j] += q2B.x*kk2.x + q2B.y*kk2.y + q2B.z*kk2.z + q2B.w*kk2.w;
            }
        }

        // ---- scale + RPE bias ----
#pragma unroll
        for (int j = 0; j < 8; j++) {
            int kc = cg + 8*j;
            int ckx = sCk[kc*2], cky = sCk[kc*2+1];
            int r0 = min(max(cqax - ckx + 128, 0), 256);
            int r1 = min(max(cqay - cky + 128, 0), 256);
            int idx = (r0*257 + r1) * NH;
            s1a[j] = s1a[j]*0.125f + __ldg(&rpe[idx + h1]);
            s2a[j] = s2a[j]*0.125f + __ldg(&rpe[idx + h2]);
            r0 = min(max(cqbx - ckx + 128, 0), 256);
            r1 = min(max(cqby - cky + 128, 0), 256);
            idx = (r0*257 + r1) * NH;
            s1b[j] = s1b[j]*0.125f + __ldg(&rpe[idx + h1]);
            s2b[j] = s2b[j]*0.125f + __ldg(&rpe[idx + h2]);
        }

        // ---- online softmax (8-lane row groups) ----
        float t1a=s1a[0], t1b=s1b[0], t2a=s2a[0], t2b=s2b[0];
#pragma unroll
        for (int j = 1; j < 8; j++) {
            t1a = fmaxf(t1a, s1a[j]); t1b = fmaxf(t1b, s1b[j]);
            t2a = fmaxf(t2a, s2a[j]); t2b = fmaxf(t2b, s2b[j]);
        }
#pragma unroll
        for (int o = 1; o < 8; o <<= 1) {
            t1a = fmaxf(t1a, __shfl_xor_sync(0xffffffffu, t1a, o));
            t1b = fmaxf(t1b, __shfl_xor_sync(0xffffffffu, t1b, o));
            t2a = fmaxf(t2a, __shfl_xor_sync(0xffffffffu, t2a, o));
            t2b = fmaxf(t2b, __shfl_xor_sync(0xffffffffu, t2b, o));
        }
        float n1a = fmaxf(m1a, t1a), n1b = fmaxf(m1b, t1b);
        float n2a = fmaxf(m2a, t2a), n2b = fmaxf(m2b, t2b);
        float c1a = __expf(m1a - n1a), c1b = __expf(m1b - n1b);
        float c2a = __expf(m2a - n2a), c2b = __expf(m2b - n2b);

        float u1a=0.f, u1b=0.f, u2a=0.f, u2b=0.f;
#pragma unroll
        for (int j = 0; j < 8; j++) {
            int kc = cg + 8*j;
            float e;
            e = __expf(s1a[j] - n1a); sS1[rr*72 + kc]      = e; u1a += e;
            e = __expf(s1b[j] - n1b); sS1[(rr+16)*72 + kc] = e; u1b += e;
            e = __expf(s2a[j] - n2a); sS2[rr*72 + kc]      = e; u2a += e;
            e = __expf(s2b[j] - n2b); sS2[(rr+16)*72 + kc] = e; u2b += e;
        }
#pragma unroll
        for (int o = 1; o < 8; o <<= 1) {
            u1a += __shfl_xor_sync(0xffffffffu, u1a, o);
            u1b += __shfl_xor_sync(0xffffffffu, u1b, o);
            u2a += __shfl_xor_sync(0xffffffffu, u2a, o);
            u2b += __shfl_xor_sync(0xffffffffu, u2b, o);
        }
        l1a = l1a*c1a + u1a; l1b = l1b*c1b + u1b;
        l2a = l2a*c2a + u2a; l2b = l2b*c2b + u2b;
        m1a = n1a; m1b = n1b; m2a = n2a; m2b = n2b;
#pragma unroll
        for (int j = 0; j < 8; j++) {
            acc1a[j]*=c1a; acc1b[j]*=c1b;
            acc2a[j]*=c2a; acc2b[j]*=c2b;
            acc3a[j]*=c2a; acc3b[j]*=c2b;
        }
        __syncwarp();

        // ---- PV accumulation ----
#pragma unroll 8
        for (int k = 0; k < 64; k++) {
            float p1A = sS1[rr*72 + k];
            float p1B = sS1[(rr+16)*72 + k];
            float p2A = sS2[rr*72 + k];
            float p2B = sS2[(rr+16)*72 + k];
            float4 va = *(float4*)&sV1[k*68 + pd0];
            float4 vb = *(float4*)&sV1[k*68 + pd0 + 4];
            float4 vc = *(float4*)&sV2[k*68 + pd0];
            float4 vd = *(float4*)&sV2[k*68 + pd0 + 4];
            ACC8(acc1a, p1A, va, vb);
            ACC8(acc1b, p1B, va, vb);
            ACC8(acc2a, p2A, va, vb);
            ACC8(acc2b, p2B, va, vb);
            ACC8(acc3a, p2A, vc, vd);
            ACC8(acc3b, p2B, vc, vd);
        }
        __syncthreads();
    }

    // ---- epilogue ----
    int qa = qb + rr, qbr = qb + rr + 16;
    float alA = alpha_map[(size_t)b*NQ + qa];
    float alB = alpha_map[(size_t)b*NQ + qbr];
    float lam = g_lam[p];

    float w1A = (1.f + alA) / l1a, w2A = -alA * lam / l2a, i2A = 1.f / l2a;
    float w1B = (1.f + alB) / l1b, w2B = -alB * lam / l2b, i2B = 1.f / l2b;

    float* oA = g_xo + ((size_t)(b*NQ + qa))*DIMC;
    float* oB = g_xo + ((size_t)(b*NQ + qbr))*DIMC;

    float4 t0, t1;
    t0.x=w1A*acc1a[0]+w2A*acc2a[0]; t0.y=w1A*acc1a[1]+w2A*acc2a[1];
    t0.z=w1A*acc1a[2]+w2A*acc2a[2]; t0.w=w1A*acc1a[3]+w2A*acc2a[3];
    t1.x=w1A*acc1a[4]+w2A*acc2a[4]; t1.y=w1A*acc1a[5]+w2A*acc2a[5];
    t1.z=w1A*acc1a[6]+w2A*acc2a[6]; t1.w=w1A*acc1a[7]+w2A*acc2a[7];
    *(float4*)(oA + h1*HD + d0)     = t0;
    *(float4*)(oA + h1*HD + d0 + 4) = t1;

    t0.x=i2A*acc3a[0]; t0.y=i2A*acc3a[1]; t0.z=i2A*acc3a[2]; t0.w=i2A*acc3a[3];
    t1.x=i2A*acc3a[4]; t1.y=i2A*acc3a[5]; t1.z=i2A*acc3a[6]; t1.w=i2A*acc3a[7];
    *(float4*)(oA + h2*HD + d0)     = t0;
    *(float4*)(oA + h2*HD + d0 + 4) = t1;

    t0.x=w1B*acc1b[0]+w2B*acc2b[0]; t0.y=w1B*acc1b[1]+w2B*acc2b[1];
    t0.z=w1B*acc1b[2]+w2B*acc2b[2]; t0.w=w1B*acc1b[3]+w2B*acc2b[3];
    t1.x=w1B*acc1b[4]+w2B*acc2b[4]; t1.y=w1B*acc1b[5]+w2B*acc2b[5];
    t1.z=w1B*acc1b[6]+w2B*acc2b[6]; t1.w=w1B*acc1b[7]+w2B*acc2b[7];
    *(float4*)(oB + h1*HD + d0)     = t0;
    *(float4*)(oB + h1*HD + d0 + 4) = t1;

    t0.x=i2B*acc3b[0]; t0.y=i2B*acc3b[1]; t0.z=i2B*acc3b[2]; t0.w=i2B*acc3b[3];
    t1.x=i2B*acc3b[4]; t1.y=i2B*acc3b[5]; t1.z=i2B*acc3b[6]; t1.w=i2B*acc3b[7];
    *(float4*)(oB + h2*HD + d0)     = t0;
    *(float4*)(oB + h2*HD + d0 + 4) = t1;
}

// ---------------- launch ---------------------------------------------------
#define ATT_SMEM ((2*32*68 + 4*64*68 + 2*32*72)*4 + 128*4)

extern "C" void kernel_launch(void* const* d_in, const int* in_sizes, int n_in,
                              void* d_out, int out_size)
{
    const float* x_q      = (const float*)d_in[0];
    const float* x_kv     = (const float*)d_in[1];
    const int*   coords_q = (const int*)  d_in[2];
    const int*   coords_k = (const int*)  d_in[3];
    const float* alpha    = (const float*)d_in[4];
    const float* Wq       = (const float*)d_in[5];
    const float* bq       = (const float*)d_in[6];
    const float* Wk       = (const float*)d_in[7];
    const float* bk       = (const float*)d_in[8];
    const float* Wv       = (const float*)d_in[9];
    const float* bv       = (const float*)d_in[10];
    const float* lq1      = (const float*)d_in[11];
    const float* lk1      = (const float*)d_in[12];
    const float* lq2      = (const float*)d_in[13];
    const float* lk2      = (const float*)d_in[14];
    const float* rpe      = (const float*)d_in[15];
    const float* Wp       = (const float*)d_in[16];
    const float* bp       = (const float*)d_in[17];
    float* out = (float*)d_out;

    cudaFuncSetAttribute(attn_kernel,
                         cudaFuncAttributeMaxDynamicSharedMemorySize, ATT_SMEM);

    lam_kernel<<<1, 32>>>(lq1, lk1, lq2, lk2);

    qkv_kernel<<<dim3(64, 8, 3), 128>>>(x_q, x_kv, Wq, bq, Wk, bk, Wv, bv);

    attn_kernel<<<dim3(32, 4, 4), 128, ATT_SMEM>>>(coords_q, coords_k, alpha, rpe);

    proj_kernel<<<dim3(64, 8), 128>>>(Wp, bp, out);
}

// round 4
// speedup vs baseline: 4.6996x; 1.1391x over previous
#include <cuda_runtime.h>

#define DIMC 512
#define NH   8
#define HD   64
#define BATCH 4
#define NQ   1024
#define NKV  1024

// mid-row pad: conflict-free float4 smem access at 8-float granularity
#define PHYS(d) ((d) + ((((d) >> 5) & 1) << 2))   // d + 4*(d>=32), d in [0,64)

// ---------------- scratch (device globals: no allocation allowed) ----------
__device__ float g_q [BATCH*NH*NQ *HD];
__device__ float g_k [BATCH*NH*NKV*HD];
__device__ float g_v [BATCH*NH*NKV*HD];
__device__ float g_xo[BATCH*NQ*DIMC];
__device__ float g_lam[NH/2];

// ---------------- lambda ---------------------------------------------------
__global__ void lam_kernel(const float* __restrict__ lq1, const float* __restrict__ lk1,
                           const float* __restrict__ lq2, const float* __restrict__ lk2)
{
    int p = threadIdx.x;
    if (p < NH/2) {
        float a = 0.f, c = 0.f;
        for (int d = 0; d < HD; d++) {
            a += lq1[p*HD+d] * lk1[p*HD+d];
            c += lq2[p*HD+d] * lk2[p*HD+d];
        }
        g_lam[p] = __expf(a) - __expf(c) + 0.8f;
    }
}

// ---------------- tf32 helpers ---------------------------------------------
__device__ __forceinline__ unsigned f2tf32(float x) {
    unsigned r;
    asm("cvt.rna.tf32.f32 %0, %1;" : "=r"(r) : "f"(x));
    return r;
}

__device__ __forceinline__ void mma_tf32(float c[4],
    unsigned a0, unsigned a1, unsigned a2, unsigned a3,
    unsigned b0, unsigned b1)
{
    asm volatile(
        "mma.sync.aligned.m16n8k8.row.col.f32.tf32.tf32.f32 "
        "{%0,%1,%2,%3},{%4,%5,%6,%7},{%8,%9},{%0,%1,%2,%3};\n"
        : "+f"(c[0]), "+f"(c[1]), "+f"(c[2]), "+f"(c[3])
        : "r"(a0), "r"(a1), "r"(a2), "r"(a3), "r"(b0), "r"(b1));
}

// ---------------- tf32 GEMM: C = A[M,K] @ W[N,K]^T + bias ------------------
// CTA tile 128x64, 4 warps (2x2), warp tile 64x32, K-step 16 (2 x k8).
// smem layout [k][m]/[k][n] with pads 136/72: STS and frag-LDS conflict-free.
// mode 0: C row-major [M,512] ; mode 1: C into [B,H,N,HD] layout
__device__ __forceinline__ void gemm_body(
    const float* __restrict__ A, const float* __restrict__ W,
    const float* __restrict__ bias, float* __restrict__ C,
    int mode, int bm, int bn)
{
    __shared__ unsigned As[16][136];   // [k][m], m<128
    __shared__ unsigned Ws[16][72];    // [k][n], n<64

    int tid  = threadIdx.x;
    int wid  = tid >> 5;
    int lane = tid & 31;
    int g    = lane >> 2;     // 0..7
    int tg   = lane & 3;      // 0..3
    int wm   = (wid >> 1) * 64;
    int wn   = (wid & 1) * 32;

    float acc[4][4][4];
#pragma unroll
    for (int mf = 0; mf < 4; mf++)
#pragma unroll
        for (int nf = 0; nf < 4; nf++)
#pragma unroll
            for (int e = 0; e < 4; e++) acc[mf][nf][e] = 0.f;

    // global load indices
    const float* Arow = A + (size_t)(bm + tid) * DIMC;          // 1 row/thread
    int nW = tid & 63, khW = tid >> 6;                          // W: n, k-half
    const float* Wrow = W + (size_t)(bn + nW) * DIMC + khW * 8;

    float4 av[4], wv[2];
#pragma unroll
    for (int i = 0; i < 4; i++) av[i] = *(const float4*)(Arow + i*4);
    wv[0] = *(const float4*)(Wrow);
    wv[1] = *(const float4*)(Wrow + 4);

    for (int k0 = 0; k0 < DIMC; k0 += 16) {
        // ---- stage (convert to tf32) ----
#pragma unroll
        for (int i = 0; i < 4; i++) {
            As[i*4+0][tid] = f2tf32(av[i].x);
            As[i*4+1][tid] = f2tf32(av[i].y);
            As[i*4+2][tid] = f2tf32(av[i].z);
            As[i*4+3][tid] = f2tf32(av[i].w);
        }
        Ws[khW*8+0][nW] = f2tf32(wv[0].x);
        Ws[khW*8+1][nW] = f2tf32(wv[0].y);
        Ws[khW*8+2][nW] = f2tf32(wv[0].z);
        Ws[khW*8+3][nW] = f2tf32(wv[0].w);
        Ws[khW*8+4][nW] = f2tf32(wv[1].x);
        Ws[khW*8+5][nW] = f2tf32(wv[1].y);
        Ws[khW*8+6][nW] = f2tf32(wv[1].z);
        Ws[khW*8+7][nW] = f2tf32(wv[1].w);
        __syncthreads();

        if (k0 + 16 < DIMC) {
#pragma unroll
            for (int i = 0; i < 4; i++)
                av[i] = *(const float4*)(Arow + k0 + 16 + i*4);
            wv[0] = *(const float4*)(Wrow + k0 + 16);
            wv[1] = *(const float4*)(Wrow + k0 + 20);
        }

        // ---- compute: 2 k8 sub-steps ----
#pragma unroll
        for (int ko = 0; ko < 16; ko += 8) {
            unsigned af[4][4], bf[4][2];
#pragma unroll
            for (int mf = 0; mf < 4; mf++) {
                int m0 = wm + mf*16 + g;
                af[mf][0] = As[ko+tg  ][m0];
                af[mf][1] = As[ko+tg  ][m0+8];
                af[mf][2] = As[ko+tg+4][m0];
                af[mf][3] = As[ko+tg+4][m0+8];
            }
#pragma unroll
            for (int nf = 0; nf < 4; nf++) {
                int n0 = wn + nf*8 + g;
                bf[nf][0] = Ws[ko+tg  ][n0];
                bf[nf][1] = Ws[ko+tg+4][n0];
            }
#pragma unroll
            for (int mf = 0; mf < 4; mf++)
#pragma unroll
                for (int nf = 0; nf < 4; nf++)
                    mma_tf32(acc[mf][nf], af[mf][0], af[mf][1], af[mf][2], af[mf][3],
                             bf[nf][0], bf[nf][1]);
        }
        __syncthreads();
    }

    // ---- epilogue ----
#pragma unroll
    for (int nf = 0; nf < 4; nf++) {
        int c0 = bn + wn + nf*8 + 2*tg;
        float b0 = bias[c0], b1 = bias[c0+1];
#pragma unroll
        for (int mf = 0; mf < 4; mf++) {
            int r0 = bm + wm + mf*16 + g;
            float2 o0 = {acc[mf][nf][0] + b0, acc[mf][nf][1] + b1};
            float2 o1 = {acc[mf][nf][2] + b0, acc[mf][nf][3] + b1};
            if (mode == 0) {
                *(float2*)(C + (size_t)r0*DIMC + c0)     = o0;
                *(float2*)(C + (size_t)(r0+8)*DIMC + c0) = o1;
            } else {
                int h = c0 >> 6, hd = c0 & 63;
                int b_  = r0 >> 10, nq = r0 & 1023;
                *(float2*)(C + (((size_t)(b_*NH + h)*NQ + nq)*HD + hd)) = o0;
                b_ = (r0+8) >> 10; nq = (r0+8) & 1023;
                *(float2*)(C + (((size_t)(b_*NH + h)*NQ + nq)*HD + hd)) = o1;
            }
        }
    }
}

__global__ __launch_bounds__(128) void qkv_kernel(
    const float* __restrict__ x_q, const float* __restrict__ x_kv,
    const float* __restrict__ Wq, const float* __restrict__ bq,
    const float* __restrict__ Wk, const float* __restrict__ bk,
    const float* __restrict__ Wv, const float* __restrict__ bv)
{
    int z = blockIdx.z;
    const float* A    = (z == 0) ? x_q : x_kv;
    const float* W    = (z == 0) ? Wq : (z == 1) ? Wk : Wv;
    const float* bias = (z == 0) ? bq : (z == 1) ? bk : bv;
    float* C          = (z == 0) ? g_q : (z == 1) ? g_k : g_v;
    gemm_body(A, W, bias, C, 1, blockIdx.x*128, blockIdx.y*64);
}

__global__ __launch_bounds__(128) void proj_kernel(
    const float* __restrict__ Wp, const float* __restrict__ bp, float* __restrict__ out)
{
    gemm_body(g_xo, Wp, bp, out, 0, blockIdx.x*128, blockIdx.y*64);
}

// ---------------- fused differential flash attention ----------------------
// grid (NQ/64, NH/2, B), 128 threads. Thread: 4 q-rows (rr+16m), 8 kv-cols
// (kc = cg + 8j interleaved), 8 out dims (d0 = cg*8).
#define ACC8(acc, pp, u, v) \
    acc[0]+=(pp)*(u).x; acc[1]+=(pp)*(u).y; acc[2]+=(pp)*(u).z; acc[3]+=(pp)*(u).w; \
    acc[4]+=(pp)*(v).x; acc[5]+=(pp)*(v).y; acc[6]+=(pp)*(v).z; acc[7]+=(pp)*(v).w;

__global__ __launch_bounds__(128, 1) void attn_kernel(
    const int* __restrict__ coords_q, const int* __restrict__ coords_k,
    const float* __restrict__ alpha_map, const float* __restrict__ rpe)
{
    extern __shared__ __align__(16) float sm[];
    float* sQ1 = sm;                  // [64][68]
    float* sQ2 = sQ1 + 64*68;
    float* sK1 = sQ2 + 64*68;         // [64][68]
    float* sK2 = sK1 + 64*68;
    float* sV1 = sK2 + 64*68;
    float* sV2 = sV1 + 64*68;
    float* sS1 = sV2 + 64*68;         // [64][72]
    float* sS2 = sS1 + 64*72;
    int*   sCk = (int*)(sS2 + 64*72); // [64][2]

    int tid = threadIdx.x;
    int qb  = blockIdx.x * 64;
    int p   = blockIdx.y;
    int b   = blockIdx.z;
    int h1  = p, h2 = p + 4;

    int cg = tid & 7;      // 0..7
    int rr = tid >> 3;     // 0..15 ; rows rr + 16m, m=0..3
    int d0 = cg * 8;
    int pd0 = PHYS(d0);

    // stage Q tiles (64 x 64 per head) with mid-pad layout
    {
        const float* q1g = g_q + ((size_t)(b*NH+h1)*NQ + qb)*HD;
        const float* q2g = g_q + ((size_t)(b*NH+h2)*NQ + qb)*HD;
        for (int c = tid; c < 1024; c += 128) {
            int row = c >> 4, seg = (c & 15) * 4;
            int po = row*68 + PHYS(seg);
            int go = row*HD + seg;
            *(float4*)&sQ1[po] = *(const float4*)(q1g + go);
            *(float4*)&sQ2[po] = *(const float4*)(q2g + go);
        }
    }

    int cqx[4], cqy[4];
#pragma unroll
    for (int m = 0; m < 4; m++) {
        cqx[m] = coords_q[((size_t)b*NQ + qb + rr + 16*m)*2];
        cqy[m] = coords_q[((size_t)b*NQ + qb + rr + 16*m)*2 + 1];
    }

    float acc1[4][8], acc2[4][8], acc3[4][8];
#pragma unroll
    for (int m = 0; m < 4; m++)
#pragma unroll
        for (int j = 0; j < 8; j++) { acc1[m][j]=0.f; acc2[m][j]=0.f; acc3[m][j]=0.f; }
    float mx1[4], l1[4], mx2[4], l2[4];
#pragma unroll
    for (int m = 0; m < 4; m++) { mx1[m]=-1e30f; l1[m]=0.f; mx2[m]=-1e30f; l2[m]=0.f; }

    const float* k1base = g_k + ((size_t)(b*NH+h1)*NKV)*HD;
    const float* k2base = g_k + ((size_t)(b*NH+h2)*NKV)*HD;
    const float* v1base = g_v + ((size_t)(b*NH+h1)*NKV)*HD;
    const float* v2base = g_v + ((size_t)(b*NH+h2)*NKV)*HD;

    for (int kb = 0; kb < NKV; kb += 64) {
        // ---- stage K/V tiles + coords ----
        for (int c = tid; c < 1024; c += 128) {
            int row = c >> 4, seg = (c & 15) * 4;
            int po = row*68 + PHYS(seg);
            int go = (kb + row)*HD + seg;
            *(float4*)&sK1[po] = *(const float4*)(k1base + go);
            *(float4*)&sK2[po] = *(const float4*)(k2base + go);
            *(float4*)&sV1[po] = *(const float4*)(v1base + go);
            *(float4*)&sV2[po] = *(const float4*)(v2base + go);
        }
        sCk[tid] = coords_k[((size_t)b*NKV + kb)*2 + tid];
        __syncthreads();

        int ckx[8], cky[8];
#pragma unroll
        for (int j = 0; j < 8; j++) {
            int kc = cg + 8*j;
            ckx[j] = sCk[kc*2]; cky[j] = sCk[kc*2+1];
        }

        // ================= head 1 =================
        {
            float s[4][8];
#pragma unroll
            for (int m = 0; m < 4; m++)
#pragma unroll
                for (int j = 0; j < 8; j++) s[m][j] = 0.f;

#pragma unroll 4
            for (int d = 0; d < 64; d += 4) {
                int pd = PHYS(d);
                float4 q[4];
#pragma unroll
                for (int m = 0; m < 4; m++) q[m] = *(float4*)&sQ1[(rr+16*m)*68 + pd];
#pragma unroll
                for (int j = 0; j < 8; j++) {
                    float4 kk = *(float4*)&sK1[(cg + 8*j)*68 + pd];
#pragma unroll
                    for (int m = 0; m < 4; m++)
                        s[m][j] += q[m].x*kk.x + q[m].y*kk.y + q[m].z*kk.z + q[m].w*kk.w;
                }
            }
#pragma unroll
            for (int m = 0; m < 4; m++) {
#pragma unroll
                for (int j = 0; j < 8; j++) {
                    int r0 = min(max(cqx[m] - ckx[j] + 128, 0), 256);
                    int r1 = min(max(cqy[m] - cky[j] + 128, 0), 256);
                    s[m][j] = s[m][j]*0.125f + __ldg(&rpe[(r0*257 + r1)*NH + h1]);
                }
                float t = s[m][0];
#pragma unroll
                for (int j = 1; j < 8; j++) t = fmaxf(t, s[m][j]);
#pragma unroll
                for (int o = 1; o < 8; o <<= 1)
                    t = fmaxf(t, __shfl_xor_sync(0xffffffffu, t, o));
                float nmax = fmaxf(mx1[m], t);
                float corr = __expf(mx1[m] - nmax);
                float su = 0.f;
#pragma unroll
                for (int j = 0; j < 8; j++) {
                    float e = __expf(s[m][j] - nmax);
                    sS1[(rr+16*m)*72 + cg + 8*j] = e;
                    su += e;
                }
#pragma unroll
                for (int o = 1; o < 8; o <<= 1)
                    su += __shfl_xor_sync(0xffffffffu, su, o);
                l1[m] = l1[m]*corr + su;
                mx1[m] = nmax;
#pragma unroll
                for (int j = 0; j < 8; j++) acc1[m][j] *= corr;
            }
        }
        // ================= head 2 =================
        {
            float s[4][8];
#pragma unroll
            for (int m = 0; m < 4; m++)
#pragma unroll
                for (int j = 0; j < 8; j++) s[m][j] = 0.f;

#pragma unroll 4
            for (int d = 0; d < 64; d += 4) {
                int pd = PHYS(d);
                float4 q[4];
#pragma unroll
                for (int m = 0; m < 4; m++) q[m] = *(float4*)&sQ2[(rr+16*m)*68 + pd];
#pragma unroll
                for (int j = 0; j < 8; j++) {
                    float4 kk = *(float4*)&sK2[(cg + 8*j)*68 + pd];
#pragma unroll
                    for (int m = 0; m < 4; m++)
                        s[m][j] += q[m].x*kk.x + q[m].y*kk.y + q[m].z*kk.z + q[m].w*kk.w;
                }
            }
#pragma unroll
            for (int m = 0; m < 4; m++) {
#pragma unroll
                for (int j = 0; j < 8; j++) {
                    int r0 = min(max(cqx[m] - ckx[j] + 128, 0), 256);
                    int r1 = min(max(cqy[m] - cky[j] + 128, 0), 256);
                    s[m][j] = s[m][j]*0.125f + __ldg(&rpe[(r0*257 + r1)*NH + h2]);
                }
                float t = s[m][0];
#pragma unroll
                for (int j = 1; j < 8; j++) t = fmaxf(t, s[m][j]);
#pragma unroll
                for (int o = 1; o < 8; o <<= 1)
                    t = fmaxf(t, __shfl_xor_sync(0xffffffffu, t, o));
                float nmax = fmaxf(mx2[m], t);
                float corr = __expf(mx2[m] - nmax);
                float su = 0.f;
#pragma unroll
                for (int j = 0; j < 8; j++) {
                    float e = __expf(s[m][j] - nmax);
                    sS2[(rr+16*m)*72 + cg + 8*j] = e;
                    su += e;
                }
#pragma unroll
                for (int o = 1; o < 8; o <<= 1)
                    su += __shfl_xor_sync(0xffffffffu, su, o);
                l2[m] = l2[m]*corr + su;
                mx2[m] = nmax;
#pragma unroll
                for (int j = 0; j < 8; j++) { acc2[m][j] *= corr; acc3[m][j] *= corr; }
            }
        }
        __syncwarp();

        // ---- PV accumulation ----
#pragma unroll 8
        for (int k = 0; k < 64; k++) {
            float4 va = *(float4*)&sV1[k*68 + pd0];
            float4 vb = *(float4*)&sV1[k*68 + pd0 + 4];
            float4 vc = *(float4*)&sV2[k*68 + pd0];
            float4 vd = *(float4*)&sV2[k*68 + pd0 + 4];
#pragma unroll
            for (int m = 0; m < 4; m++) {
                float p1 = sS1[(rr+16*m)*72 + k];
                float p2 = sS2[(rr+16*m)*72 + k];
                ACC8(acc1[m], p1, va, vb);
                ACC8(acc2[m], p2, va, vb);
                ACC8(acc3[m], p2, vc, vd);
            }
        }
        __syncthreads();
    }

    // ---- epilogue ----
    float lam = g_lam[p];
#pragma unroll
    for (int m = 0; m < 4; m++) {
        int qg = qb + rr + 16*m;
        float al = alpha_map[(size_t)b*NQ + qg];
        float w1 = (1.f + al) / l1[m];
        float w2 = -al * lam / l2[m];
        float i2 = 1.f / l2[m];
        float* o = g_xo + ((size_t)(b*NQ + qg))*DIMC;
        float4 t0, t1;
        t0.x=w1*acc1[m][0]+w2*acc2[m][0]; t0.y=w1*acc1[m][1]+w2*acc2[m][1];
        t0.z=w1*acc1[m][2]+w2*acc2[m][2]; t0.w=w1*acc1[m][3]+w2*acc2[m][3];
        t1.x=w1*acc1[m][4]+w2*acc2[m][4]; t1.y=w1*acc1[m][5]+w2*acc2[m][5];
        t1.z=w1*acc1[m][6]+w2*acc2[m][6]; t1.w=w1*acc1[m][7]+w2*acc2[m][7];
        *(float4*)(o + h1*HD + d0)     = t0;
        *(float4*)(o + h1*HD + d0 + 4) = t1;
        t0.x=i2*acc3[m][0]; t0.y=i2*acc3[m][1]; t0.z=i2*acc3[m][2]; t0.w=i2*acc3[m][3];
        t1.x=i2*acc3[m][4]; t1.y=i2*acc3[m][5]; t1.z=i2*acc3[m][6]; t1.w=i2*acc3[m][7];
        *(float4*)(o + h2*HD + d0)     = t0;
        *(float4*)(o + h2*HD + d0 + 4) = t1;
    }
}

// ---------------- launch ---------------------------------------------------
#define ATT_SMEM ((2*64*68 + 4*64*68 + 2*64*72)*4 + 128*4)

extern "C" void kernel_launch(void* const* d_in, const int* in_sizes, int n_in,
                              void* d_out, int out_size)
{
    const float* x_q      = (const float*)d_in[0];
    const float* x_kv     = (const float*)d_in[1];
    const int*   coords_q = (const int*)  d_in[2];
    const int*   coords_k = (const int*)  d_in[3];
    const float* alpha    = (const float*)d_in[4];
    const float* Wq       = (const float*)d_in[5];
    const float* bq       = (const float*)d_in[6];
    const float* Wk       = (const float*)d_in[7];
    const float* bk       = (const float*)d_in[8];
    const float* Wv       = (const float*)d_in[9];
    const float* bv       = (const float*)d_in[10];
    const float* lq1      = (const float*)d_in[11];
    const float* lk1      = (const float*)d_in[12];
    const float* lq2      = (const float*)d_in[13];
    const float* lk2      = (const float*)d_in[14];
    const float* rpe      = (const float*)d_in[15];
    const float* Wp       = (const float*)d_in[16];
    const float* bp       = (const float*)d_in[17];
    float* out = (float*)d_out;

    cudaFuncSetAttribute(attn_kernel,
                         cudaFuncAttributeMaxDynamicSharedMemorySize, ATT_SMEM);

    lam_kernel<<<1, 32>>>(lq1, lk1, lq2, lk2);

    qkv_kernel<<<dim3(32, 8, 3), 128>>>(x_q, x_kv, Wq, bq, Wk, bk, Wv, bv);

    attn_kernel<<<dim3(16, 4, 4), 128, ATT_SMEM>>>(coords_q, coords_k, alpha, rpe);

    proj_kernel<<<dim3(32, 8), 128>>>(Wp, bp, out);
}

// round 5
// speedup vs baseline: 7.6073x; 1.6187x over previous
#include <cuda_runtime.h>

#define DIMC 512
#define NH   8
#define HD   64
#define BATCH 4
#define NQ   1024
#define NKV  1024

// ---------------- scratch (device globals: no allocation allowed) ----------
__device__ float g_q [BATCH*NH*NQ *HD];
__device__ float g_k [BATCH*NH*NKV*HD];
__device__ float g_v [BATCH*NH*NKV*HD];
__device__ float g_xo[BATCH*NQ*DIMC];
__device__ float g_lam[NH/2];

// ---------------- lambda ---------------------------------------------------
__global__ void lam_kernel(const float* __restrict__ lq1, const float* __restrict__ lk1,
                           const float* __restrict__ lq2, const float* __restrict__ lk2)
{
    int p = threadIdx.x;
    if (p < NH/2) {
        float a = 0.f, c = 0.f;
        for (int d = 0; d < HD; d++) {
            a += lq1[p*HD+d] * lk1[p*HD+d];
            c += lq2[p*HD+d] * lk2[p*HD+d];
        }
        g_lam[p] = __expf(a) - __expf(c) + 0.8f;
    }
}

// ---------------- tf32 helpers ---------------------------------------------
__device__ __forceinline__ unsigned f2tf32(float x) {
    unsigned r;
    asm("cvt.rna.tf32.f32 %0, %1;" : "=r"(r) : "f"(x));
    return r;
}

__device__ __forceinline__ void mma_tf32(float c[4],
    unsigned a0, unsigned a1, unsigned a2, unsigned a3,
    unsigned b0, unsigned b1)
{
    asm volatile(
        "mma.sync.aligned.m16n8k8.row.col.f32.tf32.tf32.f32 "
        "{%0,%1,%2,%3},{%4,%5,%6,%7},{%8,%9},{%0,%1,%2,%3};\n"
        : "+f"(c[0]), "+f"(c[1]), "+f"(c[2]), "+f"(c[3])
        : "r"(a0), "r"(a1), "r"(a2), "r"(a3), "r"(b0), "r"(b1));
}

// ---------------- tf32 GEMM: C = A[M,K] @ W[N,K]^T + bias ------------------
// CTA tile 128x64, 4 warps (2x2), warp tile 64x32, K-step 16 (2 x k8).
__device__ __forceinline__ void gemm_body(
    const float* __restrict__ A, const float* __restrict__ W,
    const float* __restrict__ bias, float* __restrict__ C,
    int mode, int bm, int bn)
{
    __shared__ unsigned As[16][136];   // [k][m], m<128
    __shared__ unsigned Ws[16][72];    // [k][n], n<64

    int tid  = threadIdx.x;
    int wid  = tid >> 5;
    int lane = tid & 31;
    int g    = lane >> 2;
    int tg   = lane & 3;
    int wm   = (wid >> 1) * 64;
    int wn   = (wid & 1) * 32;

    float acc[4][4][4];
#pragma unroll
    for (int mf = 0; mf < 4; mf++)
#pragma unroll
        for (int nf = 0; nf < 4; nf++)
#pragma unroll
            for (int e = 0; e < 4; e++) acc[mf][nf][e] = 0.f;

    const float* Arow = A + (size_t)(bm + tid) * DIMC;
    int nW = tid & 63, khW = tid >> 6;
    const float* Wrow = W + (size_t)(bn + nW) * DIMC + khW * 8;

    float4 av[4], wv[2];
#pragma unroll
    for (int i = 0; i < 4; i++) av[i] = *(const float4*)(Arow + i*4);
    wv[0] = *(const float4*)(Wrow);
    wv[1] = *(const float4*)(Wrow + 4);

    for (int k0 = 0; k0 < DIMC; k0 += 16) {
#pragma unroll
        for (int i = 0; i < 4; i++) {
            As[i*4+0][tid] = f2tf32(av[i].x);
            As[i*4+1][tid] = f2tf32(av[i].y);
            As[i*4+2][tid] = f2tf32(av[i].z);
            As[i*4+3][tid] = f2tf32(av[i].w);
        }
        Ws[khW*8+0][nW] = f2tf32(wv[0].x);
        Ws[khW*8+1][nW] = f2tf32(wv[0].y);
        Ws[khW*8+2][nW] = f2tf32(wv[0].z);
        Ws[khW*8+3][nW] = f2tf32(wv[0].w);
        Ws[khW*8+4][nW] = f2tf32(wv[1].x);
        Ws[khW*8+5][nW] = f2tf32(wv[1].y);
        Ws[khW*8+6][nW] = f2tf32(wv[1].z);
        Ws[khW*8+7][nW] = f2tf32(wv[1].w);
        __syncthreads();

        if (k0 + 16 < DIMC) {
#pragma unroll
            for (int i = 0; i < 4; i++)
                av[i] = *(const float4*)(Arow + k0 + 16 + i*4);
            wv[0] = *(const float4*)(Wrow + k0 + 16);
            wv[1] = *(const float4*)(Wrow + k0 + 20);
        }

#pragma unroll
        for (int ko = 0; ko < 16; ko += 8) {
            unsigned af[4][4], bf[4][2];
#pragma unroll
            for (int mf = 0; mf < 4; mf++) {
                int m0 = wm + mf*16 + g;
                af[mf][0] = As[ko+tg  ][m0];
                af[mf][1] = As[ko+tg  ][m0+8];
                af[mf][2] = As[ko+tg+4][m0];
                af[mf][3] = As[ko+tg+4][m0+8];
            }
#pragma unroll
            for (int nf = 0; nf < 4; nf++) {
                int n0 = wn + nf*8 + g;
                bf[nf][0] = Ws[ko+tg  ][n0];
                bf[nf][1] = Ws[ko+tg+4][n0];
            }
#pragma unroll
            for (int mf = 0; mf < 4; mf++)
#pragma unroll
                for (int nf = 0; nf < 4; nf++)
                    mma_tf32(acc[mf][nf], af[mf][0], af[mf][1], af[mf][2], af[mf][3],
                             bf[nf][0], bf[nf][1]);
        }
        __syncthreads();
    }

#pragma unroll
    for (int nf = 0; nf < 4; nf++) {
        int c0 = bn + wn + nf*8 + 2*tg;
        float b0 = bias[c0], b1 = bias[c0+1];
#pragma unroll
        for (int mf = 0; mf < 4; mf++) {
            int r0 = bm + wm + mf*16 + g;
            float2 o0 = {acc[mf][nf][0] + b0, acc[mf][nf][1] + b1};
            float2 o1 = {acc[mf][nf][2] + b0, acc[mf][nf][3] + b1};
            if (mode == 0) {
                *(float2*)(C + (size_t)r0*DIMC + c0)     = o0;
                *(float2*)(C + (size_t)(r0+8)*DIMC + c0) = o1;
            } else {
                int h = c0 >> 6, hd = c0 & 63;
                int b_  = r0 >> 10, nq = r0 & 1023;
                *(float2*)(C + (((size_t)(b_*NH + h)*NQ + nq)*HD + hd)) = o0;
                b_ = (r0+8) >> 10; nq = (r0+8) & 1023;
                *(float2*)(C + (((size_t)(b_*NH + h)*NQ + nq)*HD + hd)) = o1;
            }
        }
    }
}

__global__ __launch_bounds__(128) void qkv_kernel(
    const float* __restrict__ x_q, const float* __restrict__ x_kv,
    const float* __restrict__ Wq, const float* __restrict__ bq,
    const float* __restrict__ Wk, const float* __restrict__ bk,
    const float* __restrict__ Wv, const float* __restrict__ bv)
{
    int z = blockIdx.z;
    const float* A    = (z == 0) ? x_q : x_kv;
    const float* W    = (z == 0) ? Wq : (z == 1) ? Wk : Wv;
    const float* bias = (z == 0) ? bq : (z == 1) ? bk : bv;
    float* C          = (z == 0) ? g_q : (z == 1) ? g_k : g_v;
    gemm_body(A, W, bias, C, 1, blockIdx.x*128, blockIdx.y*64);
}

__global__ __launch_bounds__(128) void proj_kernel(
    const float* __restrict__ Wp, const float* __restrict__ bp, float* __restrict__ out)
{
    gemm_body(g_xo, Wp, bp, out, 0, blockIdx.x*128, blockIdx.y*64);
}

// ---------------- tensor-core differential flash attention -----------------
// grid (NQ/64, NH/2, B), 256 threads (8 warps).
// Score duty : warp w -> head (w>>2), m-strip (w&3)*16   (16 q-rows x 64 kv)
// PV duty    : warp w -> m-strip (w>>1)*16, n-half (w&1)*32
// smem tiles stride 68 (=4 mod 32): all mma fragment LDS conflict-free.
#define ASTRIDE 68

__global__ __launch_bounds__(256, 1) void attn_kernel(
    const int* __restrict__ coords_q, const int* __restrict__ coords_k,
    const float* __restrict__ alpha_map, const float* __restrict__ rpe)
{
    extern __shared__ __align__(16) unsigned su[];
    unsigned* sQ1 = su;                 // [64][68] tf32
    unsigned* sQ2 = sQ1 + 64*ASTRIDE;
    unsigned* sK1 = sQ2 + 64*ASTRIDE;
    unsigned* sK2 = sK1 + 64*ASTRIDE;
    unsigned* sV1 = sK2 + 64*ASTRIDE;
    unsigned* sV2 = sV1 + 64*ASTRIDE;
    unsigned* sS1 = sV2 + 64*ASTRIDE;   // P tiles (tf32)
    unsigned* sS2 = sS1 + 64*ASTRIDE;
    float* sC1 = (float*)(sS2 + 64*ASTRIDE);  // [64] per-tile corrections
    float* sC2 = sC1 + 64;
    float* sL1 = sC2 + 64;                    // [64] final l
    float* sL2 = sL1 + 64;
    int*   sCk = (int*)(sL2 + 64);            // [64][2]

    int tid  = threadIdx.x;
    int w    = tid >> 5;
    int lane = tid & 31;
    int g    = lane >> 2;
    int tg   = lane & 3;

    int qb = blockIdx.x * 64;
    int p  = blockIdx.y;
    int b  = blockIdx.z;
    int h1 = p, h2 = p + 4;

    // roles
    int sh  = w >> 2;          // score head (0 -> h1, 1 -> h2)
    int sm0 = (w & 3) * 16;    // score m-strip
    int pm0 = (w >> 1) * 16;   // PV m-strip
    int pn0 = (w & 1) * 32;    // PV n-half

    // ---- stage Q (tf32) ----
    {
        const float* q1g = g_q + ((size_t)(b*NH+h1)*NQ + qb)*HD;
        const float* q2g = g_q + ((size_t)(b*NH+h2)*NQ + qb)*HD;
        for (int c = tid; c < 1024; c += 256) {
            int row = c >> 4, seg = (c & 15) * 4;
            float4 v1 = *(const float4*)(q1g + row*HD + seg);
            float4 v2 = *(const float4*)(q2g + row*HD + seg);
            *(uint4*)&sQ1[row*ASTRIDE+seg] =
                make_uint4(f2tf32(v1.x), f2tf32(v1.y), f2tf32(v1.z), f2tf32(v1.w));
            *(uint4*)&sQ2[row*ASTRIDE+seg] =
                make_uint4(f2tf32(v2.x), f2tf32(v2.y), f2tf32(v2.z), f2tf32(v2.w));
        }
    }

    // score-duty per-thread query coords (rows sm0+g, sm0+g+8)
    int sr0 = sm0 + g, sr1 = sm0 + g + 8;
    int cqx0 = coords_q[((size_t)b*NQ + qb + sr0)*2];
    int cqy0 = coords_q[((size_t)b*NQ + qb + sr0)*2 + 1];
    int cqx1 = coords_q[((size_t)b*NQ + qb + sr1)*2];
    int cqy1 = coords_q[((size_t)b*NQ + qb + sr1)*2 + 1];
    int hh = sh ? h2 : h1;

    float mOld0 = -1e30f, mOld1 = -1e30f, lRun0 = 0.f, lRun1 = 0.f;

    float pacc[3][4][4];
#pragma unroll
    for (int pr = 0; pr < 3; pr++)
#pragma unroll
        for (int nt = 0; nt < 4; nt++)
#pragma unroll
            for (int e = 0; e < 4; e++) pacc[pr][nt][e] = 0.f;

    const float* k1base = g_k + ((size_t)(b*NH+h1)*NKV)*HD;
    const float* k2base = g_k + ((size_t)(b*NH+h2)*NKV)*HD;
    const float* v1base = g_v + ((size_t)(b*NH+h1)*NKV)*HD;
    const float* v2base = g_v + ((size_t)(b*NH+h2)*NKV)*HD;

    const unsigned* Qs  = sh ? sQ2 : sQ1;
    const unsigned* Ks  = sh ? sK2 : sK1;
    unsigned* Ss        = sh ? sS2 : sS1;
    float* sCa          = sh ? sC2 : sC1;

    for (int kb = 0; kb < NKV; kb += 64) {
        // ---- stage K/V (tf32) + coords ----
        for (int c = tid; c < 1024; c += 256) {
            int row = c >> 4, seg = (c & 15) * 4;
            int go = (kb + row)*HD + seg;
            float4 a1 = *(const float4*)(k1base + go);
            float4 a2 = *(const float4*)(k2base + go);
            float4 a3 = *(const float4*)(v1base + go);
            float4 a4 = *(const float4*)(v2base + go);
            *(uint4*)&sK1[row*ASTRIDE+seg] =
                make_uint4(f2tf32(a1.x), f2tf32(a1.y), f2tf32(a1.z), f2tf32(a1.w));
            *(uint4*)&sK2[row*ASTRIDE+seg] =
                make_uint4(f2tf32(a2.x), f2tf32(a2.y), f2tf32(a2.z), f2tf32(a2.w));
            *(uint4*)&sV1[row*ASTRIDE+seg] =
                make_uint4(f2tf32(a3.x), f2tf32(a3.y), f2tf32(a3.z), f2tf32(a3.w));
            *(uint4*)&sV2[row*ASTRIDE+seg] =
                make_uint4(f2tf32(a4.x), f2tf32(a4.y), f2tf32(a4.z), f2tf32(a4.w));
        }
        if (tid < 128) sCk[tid] = coords_k[((size_t)b*NKV + kb)*2 + tid];
        __syncthreads();

        // ---- scores: m16 strip x 64 kv via mma ----
        float sc[8][4];
#pragma unroll
        for (int nt = 0; nt < 8; nt++)
#pragma unroll
            for (int e = 0; e < 4; e++) sc[nt][e] = 0.f;

#pragma unroll
        for (int ko = 0; ko < 64; ko += 8) {
            unsigned a0 = Qs[(sm0+g  )*ASTRIDE + ko+tg];
            unsigned a1 = Qs[(sm0+g+8)*ASTRIDE + ko+tg];
            unsigned a2 = Qs[(sm0+g  )*ASTRIDE + ko+tg+4];
            unsigned a3 = Qs[(sm0+g+8)*ASTRIDE + ko+tg+4];
#pragma unroll
            for (int nt = 0; nt < 8; nt++) {
                unsigned b0 = Ks[(8*nt+g)*ASTRIDE + ko+tg];
                unsigned b1 = Ks[(8*nt+g)*ASTRIDE + ko+tg+4];
                mma_tf32(sc[nt], a0, a1, a2, a3, b0, b1);
            }
        }

        // ---- scale + RPE bias ----
#pragma unroll
        for (int nt = 0; nt < 8; nt++) {
#pragma unroll
            for (int u = 0; u < 2; u++) {
                int col = 8*nt + 2*tg + u;
                int ckx = sCk[col*2], cky = sCk[col*2+1];
                int r0 = min(max(cqx0 - ckx + 128, 0), 256);
                int r1 = min(max(cqy0 - cky + 128, 0), 256);
                sc[nt][u] = sc[nt][u]*0.125f + __ldg(&rpe[(r0*257 + r1)*NH + hh]);
                r0 = min(max(cqx1 - ckx + 128, 0), 256);
                r1 = min(max(cqy1 - cky + 128, 0), 256);
                sc[nt][2+u] = sc[nt][2+u]*0.125f + __ldg(&rpe[(r0*257 + r1)*NH + hh]);
            }
        }

        // ---- online softmax (rows sr0, sr1; quad reduction) ----
        float rm0 = sc[0][0], rm1 = sc[0][2];
#pragma unroll
        for (int nt = 0; nt < 8; nt++) {
            rm0 = fmaxf(rm0, fmaxf(sc[nt][0], sc[nt][1]));
            rm1 = fmaxf(rm1, fmaxf(sc[nt][2], sc[nt][3]));
        }
#pragma unroll
        for (int o = 1; o < 4; o <<= 1) {
            rm0 = fmaxf(rm0, __shfl_xor_sync(0xffffffffu, rm0, o));
            rm1 = fmaxf(rm1, __shfl_xor_sync(0xffffffffu, rm1, o));
        }
        float nm0 = fmaxf(mOld0, rm0), nm1 = fmaxf(mOld1, rm1);
        float corr0 = __expf(mOld0 - nm0), corr1 = __expf(mOld1 - nm1);

        float sum0 = 0.f, sum1 = 0.f;
#pragma unroll
        for (int nt = 0; nt < 8; nt++) {
#pragma unroll
            for (int u = 0; u < 2; u++) {
                int col = 8*nt + 2*tg + u;
                float e0 = __expf(sc[nt][u]   - nm0); sum0 += e0;
                float e1 = __expf(sc[nt][2+u] - nm1); sum1 += e1;
                Ss[sr0*ASTRIDE + col] = f2tf32(e0);
                Ss[sr1*ASTRIDE + col] = f2tf32(e1);
            }
        }
#pragma unroll
        for (int o = 1; o < 4; o <<= 1) {
            sum0 += __shfl_xor_sync(0xffffffffu, sum0, o);
            sum1 += __shfl_xor_sync(0xffffffffu, sum1, o);
        }
        lRun0 = lRun0*corr0 + sum0;
        lRun1 = lRun1*corr1 + sum1;
        mOld0 = nm0; mOld1 = nm1;
        if (tg == 0) { sCa[sr0] = corr0; sCa[sr1] = corr1; }
        __syncthreads();

        // ---- PV: rescale accumulators, then mma-accumulate this tile ----
        float c1r0 = sC1[pm0+g], c1r1 = sC1[pm0+g+8];
        float c2r0 = sC2[pm0+g], c2r1 = sC2[pm0+g+8];
#pragma unroll
        for (int nt = 0; nt < 4; nt++) {
            pacc[0][nt][0] *= c1r0; pacc[0][nt][1] *= c1r0;
            pacc[0][nt][2] *= c1r1; pacc[0][nt][3] *= c1r1;
            pacc[1][nt][0] *= c2r0; pacc[1][nt][1] *= c2r0;
            pacc[1][nt][2] *= c2r1; pacc[1][nt][3] *= c2r1;
            pacc[2][nt][0] *= c2r0; pacc[2][nt][1] *= c2r0;
            pacc[2][nt][2] *= c2r1; pacc[2][nt][3] *= c2r1;
        }

#pragma unroll
        for (int ko = 0; ko < 64; ko += 8) {
            unsigned p1a0 = sS1[(pm0+g  )*ASTRIDE + ko+tg];
            unsigned p1a1 = sS1[(pm0+g+8)*ASTRIDE + ko+tg];
            unsigned p1a2 = sS1[(pm0+g  )*ASTRIDE + ko+tg+4];
            unsigned p1a3 = sS1[(pm0+g+8)*ASTRIDE + ko+tg+4];
            unsigned p2a0 = sS2[(pm0+g  )*ASTRIDE + ko+tg];
            unsigned p2a1 = sS2[(pm0+g+8)*ASTRIDE + ko+tg];
            unsigned p2a2 = sS2[(pm0+g  )*ASTRIDE + ko+tg+4];
            unsigned p2a3 = sS2[(pm0+g+8)*ASTRIDE + ko+tg+4];
#pragma unroll
            for (int nt = 0; nt < 4; nt++) {
                int n0 = pn0 + 8*nt;
                unsigned bv10 = sV1[(ko+tg  )*ASTRIDE + n0+g];
                unsigned bv11 = sV1[(ko+tg+4)*ASTRIDE + n0+g];
                unsigned bv20 = sV2[(ko+tg  )*ASTRIDE + n0+g];
                unsigned bv21 = sV2[(ko+tg+4)*ASTRIDE + n0+g];
                mma_tf32(pacc[0][nt], p1a0, p1a1, p1a2, p1a3, bv10, bv11);
                mma_tf32(pacc[1][nt], p2a0, p2a1, p2a2, p2a3, bv10, bv11);
                mma_tf32(pacc[2][nt], p2a0, p2a1, p2a2, p2a3, bv20, bv21);
            }
        }
        __syncthreads();
    }

    // publish final l
    if (tg == 0) {
        if (sh == 0) { sL1[sr0] = lRun0; sL1[sr1] = lRun1; }
        else         { sL2[sr0] = lRun0; sL2[sr1] = lRun1; }
    }
    __syncthreads();

    // ---- epilogue (PV layout) ----
    float lam = g_lam[p];
    int r_0 = pm0 + g, r_1 = pm0 + g + 8;
    float l1_0 = sL1[r_0], l1_1 = sL1[r_1];
    float l2_0 = sL2[r_0], l2_1 = sL2[r_1];
    float al0 = alpha_map[(size_t)b*NQ + qb + r_0];
    float al1 = alpha_map[(size_t)b*NQ + qb + r_1];
    float w1_0 = (1.f + al0) / l1_0, w2_0 = -al0 * lam / l2_0, i2_0 = 1.f / l2_0;
    float w1_1 = (1.f + al1) / l1_1, w2_1 = -al1 * lam / l2_1, i2_1 = 1.f / l2_1;

    float* o0 = g_xo + ((size_t)(b*NQ + qb + r_0))*DIMC;
    float* o1 = g_xo + ((size_t)(b*NQ + qb + r_1))*DIMC;
#pragma unroll
    for (int nt = 0; nt < 4; nt++) {
        int col = pn0 + 8*nt + 2*tg;
        float2 t;
        t.x = w1_0*pacc[0][nt][0] + w2_0*pacc[1][nt][0];
        t.y = w1_0*pacc[0][nt][1] + w2_0*pacc[1][nt][1];
        *(float2*)(o0 + h1*HD + col) = t;
        t.x = w1_1*pacc[0][nt][2] + w2_1*pacc[1][nt][2];
        t.y = w1_1*pacc[0][nt][3] + w2_1*pacc[1][nt][3];
        *(float2*)(o1 + h1*HD + col) = t;
        t.x = i2_0*pacc[2][nt][0];
        t.y = i2_0*pacc[2][nt][1];
        *(float2*)(o0 + h2*HD + col) = t;
        t.x = i2_1*pacc[2][nt][2];
        t.y = i2_1*pacc[2][nt][3];
        *(float2*)(o1 + h2*HD + col) = t;
    }
}

// ---------------- launch ---------------------------------------------------
#define ATT_SMEM (8*64*ASTRIDE*4 + 4*64*4 + 128*4)

extern "C" void kernel_launch(void* const* d_in, const int* in_sizes, int n_in,
                              void* d_out, int out_size)
{
    const float* x_q      = (const float*)d_in[0];
    const float* x_kv     = (const float*)d_in[1];
    const int*   coords_q = (const int*)  d_in[2];
    const int*   coords_k = (const int*)  d_in[3];
    const float* alpha    = (const float*)d_in[4];
    const float* Wq       = (const float*)d_in[5];
    const float* bq       = (const float*)d_in[6];
    const float* Wk       = (const float*)d_in[7];
    const float* bk       = (const float*)d_in[8];
    const float* Wv       = (const float*)d_in[9];
    const float* bv       = (const float*)d_in[10];
    const float* lq1      = (const float*)d_in[11];
    const float* lk1      = (const float*)d_in[12];
    const float* lq2      = (const float*)d_in[13];
    const float* lk2      = (const float*)d_in[14];
    const float* rpe      = (const float*)d_in[15];
    const float* Wp       = (const float*)d_in[16];
    const float* bp       = (const float*)d_in[17];
    float* out = (float*)d_out;

    cudaFuncSetAttribute(attn_kernel,
                         cudaFuncAttributeMaxDynamicSharedMemorySize, ATT_SMEM);

    lam_kernel<<<1, 32>>>(lq1, lk1, lq2, lk2);

    qkv_kernel<<<dim3(32, 8, 3), 128>>>(x_q, x_kv, Wq, bq, Wk, bk, Wv, bv);

    attn_kernel<<<dim3(16, 4, 4), 256, ATT_SMEM>>>(coords_q, coords_k, alpha, rpe);

    proj_kernel<<<dim3(32, 8), 128>>>(Wp, bp, out);
}